// round 14
// baseline (speedup 1.0000x reference)
#include <cuda_runtime.h>
#include <cuda_bf16.h>
#include <stdint.h>
#include <math.h>

#define P 8192
#define D 256
#define C_L2T 20.60992915555662f   // log2(e)/0.07
#define LN2F  0.6931471805599453f
#define NCTA 148
#define NITEMS 1024                // 64 row-tiles x 16 chunk-blocks (512 keys each)
#define FINB 64

// ---------------- device scratch (allocation-free) ----------------
__device__ int g_is64;
__device__ __align__(16) uint32_t g_Qh[P * 128];          // bf16x2 packed rows
// K in mma-B-fragment order: [kb(256)][kt(16)][u4(2)][lane(32)][4 u32] + pad
__device__ __align__(16) uint32_t g_Kf[256 * 4096 + 512];
// ksq in C-fragment order: [kb(256)][lane(32)][8 floats]
__device__ __align__(16) float g_ksqf[256 * 256];
__device__ float g_qsq[P];
__device__ float g_ksq[P];
__device__ __align__(16) float g_pm[P * 16];   // per-row, per-segment partial max
__device__ __align__(16) float g_ps[P * 16];   // partial sum
__device__ float g_pd[P];
__device__ float g_bsum[FINB];

// ---------------- smem layout ----------------
// [0, 67584)        Q buf 0 (128 rows x 528B)
// [67584, 135168)   Q buf 1
// [135168, 200704)  acc ring: 2 slots x 32768 B (8 warps x 4096)
// [200704, 202752)  part: float2[2][128]
#define QBUF_BYTES 67584
#define OFF_ACC    135168
#define ACC_SLOT   32768
#define OFF_PART   200704
#define SMEM_TOTAL 202752

// ---------------- PTX helpers (base-PTX only, sm_103-safe) ----------------
__device__ __forceinline__ uint32_t smem_u32(const void* p){
    uint32_t a;
    asm("{ .reg .u64 t; cvta.to.shared.u64 t, %1; cvt.u32.u64 %0, t; }" : "=r"(a) : "l"(p));
    return a;
}
__device__ __forceinline__ void cpa16(uint32_t dst, const void* src){
    asm volatile("cp.async.cg.shared.global [%0], [%1], 16;" :: "r"(dst), "l"(src));
}
#define CP_COMMIT asm volatile("cp.async.commit_group;" ::: "memory")
#define CP_WAIT0  asm volatile("cp.async.wait_group 0;" ::: "memory")

__device__ __forceinline__ void ldm_x4(uint32_t& r0, uint32_t& r1, uint32_t& r2, uint32_t& r3,
                                       uint32_t addr){
    asm volatile("ldmatrix.sync.aligned.m8n8.x4.shared.b16 {%0,%1,%2,%3}, [%4];"
                 : "=r"(r0), "=r"(r1), "=r"(r2), "=r"(r3) : "r"(addr));
}
__device__ __forceinline__ void mma_bf16(float c[4], const uint32_t a[4],
                                         uint32_t b0, uint32_t b1){
    asm volatile(
        "mma.sync.aligned.m16n8k16.row.col.f32.bf16.bf16.f32 "
        "{%0,%1,%2,%3}, {%4,%5,%6,%7}, {%8,%9}, {%0,%1,%2,%3};"
        : "+f"(c[0]), "+f"(c[1]), "+f"(c[2]), "+f"(c[3])
        : "r"(a[0]), "r"(a[1]), "r"(a[2]), "r"(a[3]), "r"(b0), "r"(b1));
}
__device__ __forceinline__ float ex2a(float x){ float y; asm("ex2.approx.f32 %0, %1;" : "=f"(y) : "f"(x)); return y; }
__device__ __forceinline__ float sqrta(float x){ float y; asm("sqrt.approx.f32 %0, %1;" : "=f"(y) : "f"(x)); return y; }
__device__ __forceinline__ uint32_t f2bf_bits(float x){
    return (uint32_t)__bfloat16_as_ushort(__float2bfloat16(x));
}

// ---------------- 1: dtype detection (int64 vs int32 map) ----------------
__global__ void detect_kernel(const int* __restrict__ m32){
    __shared__ int nz;
    if (threadIdx.x == 0) nz = 0;
    __syncthreads();
    int any = 0;
    for (int i = 1 + 2*(int)threadIdx.x; i < P; i += 2*(int)blockDim.x)
        if (m32[i] != 0) any = 1;
    if (any) atomicOr(&nz, 1);
    __syncthreads();
    if (threadIdx.x == 0) g_is64 = (nz == 0) ? 1 : 0;
}

// ---------------- 2: gather Q -> bf16 pack + qsq + ksq + partial-slot init ----------------
__global__ void prepQ_kernel(const float* __restrict__ f1, const float* __restrict__ f2,
                             const void* __restrict__ map){
    const int r = blockIdx.x, t = threadIdx.x;
    long long idx = g_is64 ? ((const long long*)map)[r]
                           : (long long)((const int*)map)[r];
    float2 q = reinterpret_cast<const float2*>(f1 + idx * (long long)D)[t];
    g_Qh[r*128 + t] = f2bf_bits(q.x) | (f2bf_bits(q.y) << 16);
    float2 k = reinterpret_cast<const float2*>(f2 + (long long)r * D)[t];
    if (t < 16){ g_pm[r*16 + t] = -INFINITY; g_ps[r*16 + t] = 0.f; }
    float qs = q.x*q.x + q.y*q.y;
    float ks = k.x*k.x + k.y*k.y;
    #pragma unroll
    for (int o = 16; o; o >>= 1){
        qs += __shfl_xor_sync(0xffffffffu, qs, o);
        ks += __shfl_xor_sync(0xffffffffu, ks, o);
    }
    __shared__ float sq[4], sk[4];
    if ((t & 31) == 0){ sq[t >> 5] = qs; sk[t >> 5] = ks; }
    __syncthreads();
    if (t == 0){
        g_qsq[r] = sq[0] + sq[1] + sq[2] + sq[3];
        g_ksq[r] = sk[0] + sk[1] + sk[2] + sk[3];
    }
}

// ---------------- 3: pack K into mma B-fragment layout + fragment-ordered ksq ----------------
__global__ void prepKf_kernel(const float* __restrict__ f2){
    const int kb = blockIdx.x;
    for (int idx = threadIdx.x; idx < 4096; idx += 256){
        int kt  = idx >> 8;
        int rem = idx & 255;
        int u4  = rem >> 7;
        int lam = (rem >> 2) & 31;
        int p   = rem & 3;
        int nt  = u4*2 + (p >> 1);
        int w   = p & 1;
        int n = kb*32 + nt*8 + (lam >> 2);
        int k = kt*16 + w*8 + (lam & 3)*2;
        const float* src = f2 + (long long)n * D + k;
        g_Kf[kb*4096 + idx] = f2bf_bits(src[0]) | (f2bf_bits(src[1]) << 16);
    }
    {
        int lam = threadIdx.x >> 3, i = threadIdx.x & 7;
        int nt = i >> 1, j = i & 1;
        g_ksqf[kb*256 + threadIdx.x] = g_ksq[kb*32 + nt*8 + (lam & 3)*2 + j];
    }
}

// ---------------- Q tile loader (cooperative, cp.async) ----------------
__device__ __forceinline__ void load_q_tile(uint32_t dstbase, int rt, int tid){
    const int m0 = rt << 7;
    for (int j = tid; j < 128*32; j += 512){
        int row = j >> 5, c2 = j & 31;
        cpa16(dstbase + (uint32_t)(row*528 + c2*16), &g_Qh[(size_t)(m0+row)*128 + c2*4]);
    }
}

// ---------------- 4: main kernel — warp-specialized producer/consumer ----------------
// 148 persistent CTAs, 512 threads = 16 warps.
// Warps 0-7  (MMA):      (rw = w>>1 rows 32, cwp = w&1 keys 32 of each 64-key chunk)
// Warps 8-15 (epilogue): epi warp e reads acc of MMA warp w=e (same rw/cwp mapping).
// Per 64-key chunk: MMA computes chunk c -> smem buf(c&1); epi consumes chunk c-1
// from buf((c-1)&1); one __syncthreads per chunk. Tensor and MUFU overlap by construction.
__global__ void __launch_bounds__(512, 1) nce_main_kernel(){
    extern __shared__ __align__(16) uint8_t sm[];
    const uint32_t sb = smem_u32(sm);
    const int tid = threadIdx.x;
    const int lane = tid & 31, wid = tid >> 5;
    const bool is_mma = (wid < 8);
    const int e  = wid & 7;            // role-local warp index
    const int rw = e >> 1, cwp = e & 1;
    const int g = lane >> 2, t = lane & 3;
    const int bid = blockIdx.x;

    int wi = (bid * NITEMS) / NCTA;
    const int we = ((bid + 1) * NITEMS) / NCTA;

    const uint32_t a_off = (uint32_t)((rw*32 + (lane & 15))*528 + (lane >> 4)*16);
    const uint4*  Bb = reinterpret_cast<const uint4*>(g_Kf);
    const float4* Kb = reinterpret_cast<const float4*>(g_ksqf);
    float2* part = (float2*)(sm + OFF_PART);
    // acc slot base for this warp's tile (producer and consumer use same offsets)
    float4* accw0 = (float4*)(sm + OFF_ACC + e*4096);
    float4* accw1 = (float4*)(sm + OFF_ACC + ACC_SLOT + e*4096);

    int buf = 0;
    load_q_tile(sb, wi >> 4, tid);
    CP_COMMIT; CP_WAIT0;
    __syncthreads();

    while (wi < we){
        const int rt = wi >> 4;
        const int cb_start = wi & 15;
        int seg_end = (rt + 1) << 4;
        if (seg_end > we) seg_end = we;
        const int ncb = seg_end - wi;
        const int nch = ncb * 8;            // 64-key chunks in this segment
        const bool havenext = (seg_end < we);
        if (havenext){ load_q_tile(sb + (uint32_t)(buf^1)*QBUF_BYTES, seg_end >> 4, tid); CP_COMMIT; }

        const int m0 = rt << 7;
        const int kbase = cb_start * 16;    // first 32-key block of segment
        const int diag_kb = rt*4 + rw;
        const uint32_t a_base = sb + (uint32_t)buf*QBUF_BYTES + a_off;

        // epilogue state
        float qs[2][2], mrun[2][2], srun[2][2];
        if (!is_mma){
            #pragma unroll
            for (int mt = 0; mt < 2; mt++){
                qs[mt][0] = g_qsq[m0 + rw*32 + mt*16 + g];
                qs[mt][1] = g_qsq[m0 + rw*32 + mt*16 + g + 8];
                mrun[mt][0] = mrun[mt][1] = -INFINITY;
                srun[mt][0] = srun[mt][1] = 0.f;
            }
        }

        // producer B pipeline priming (kt0, kt1 of first chunk's kb)
        uint4 blo[2], bhi[2];
        if (is_mma){
            const uint4* p0 = Bb + (size_t)(kbase + cwp)*1024 + lane;
            blo[0] = __ldg(p0);      bhi[0] = __ldg(p0 + 32);
            blo[1] = __ldg(p0 + 64); bhi[1] = __ldg(p0 + 96);
        }

        for (int cc = 0; cc <= nch; cc++){
            if (is_mma && cc < nch){
                const int kb  = kbase + cc*2 + cwp;
                const int kbn = kbase + ((cc + 1 < nch) ? (cc + 1) : cc)*2 + cwp;
                const uint4* bp  = Bb + (size_t)kb*1024 + lane;
                const uint4* npc = Bb + (size_t)kbn*1024 + lane;

                float acc[2][4][4];
                #pragma unroll
                for (int mt = 0; mt < 2; mt++)
                    #pragma unroll
                    for (int nt = 0; nt < 4; nt++)
                        #pragma unroll
                        for (int q4 = 0; q4 < 4; q4++) acc[mt][nt][q4] = 0.f;

                #pragma unroll
                for (int kt = 0; kt < 16; kt++){
                    uint4 clo = blo[kt & 1], chi = bhi[kt & 1];
                    const uint4* np = (kt < 14) ? (bp + (kt + 2)*64) : (npc + (kt - 14)*64);
                    blo[kt & 1] = __ldg(np); bhi[kt & 1] = __ldg(np + 32);
                    uint32_t A0[4], A1[4];
                    ldm_x4(A0[0], A0[1], A0[2], A0[3], a_base + (uint32_t)(kt*32));
                    ldm_x4(A1[0], A1[1], A1[2], A1[3], a_base + (uint32_t)(16*528 + kt*32));
                    mma_bf16(acc[0][0], A0, clo.x, clo.y);
                    mma_bf16(acc[0][1], A0, clo.z, clo.w);
                    mma_bf16(acc[0][2], A0, chi.x, chi.y);
                    mma_bf16(acc[0][3], A0, chi.z, chi.w);
                    mma_bf16(acc[1][0], A1, clo.x, clo.y);
                    mma_bf16(acc[1][1], A1, clo.z, clo.w);
                    mma_bf16(acc[1][2], A1, chi.x, chi.y);
                    mma_bf16(acc[1][3], A1, chi.z, chi.w);
                }

                // hand off acc -> smem ring (conflict-free STS.128)
                float4* dst = (cc & 1) ? accw1 : accw0;
                #pragma unroll
                for (int mt = 0; mt < 2; mt++)
                    #pragma unroll
                    for (int nt = 0; nt < 4; nt++)
                        dst[(mt*4 + nt)*32 + lane] =
                            make_float4(acc[mt][nt][0], acc[mt][nt][1],
                                        acc[mt][nt][2], acc[mt][nt][3]);
            }
            if (!is_mma && cc > 0){
                const int pk  = cc - 1;
                const int kbp = kbase + pk*2 + cwp;
                const float4* src = (pk & 1) ? accw1 : accw0;

                float acc[2][4][4];
                #pragma unroll
                for (int mt = 0; mt < 2; mt++)
                    #pragma unroll
                    for (int nt = 0; nt < 4; nt++){
                        float4 x = src[(mt*4 + nt)*32 + lane];
                        acc[mt][nt][0] = x.x; acc[mt][nt][1] = x.y;
                        acc[mt][nt][2] = x.z; acc[mt][nt][3] = x.w;
                    }

                const float4* kp = Kb + (size_t)kbp*64 + lane*2;
                float4 kq0 = __ldg(kp), kq1 = __ldg(kp + 1);
                float kq[8] = {kq0.x, kq0.y, kq0.z, kq0.w, kq1.x, kq1.y, kq1.z, kq1.w};
                const bool has_diag = (kbp == diag_kb);
                #pragma unroll
                for (int mt = 0; mt < 2; mt++){
                    #pragma unroll
                    for (int h = 0; h < 2; h++){
                        const int rloc = rw*32 + mt*16 + g + 8*h;
                        float v[8];
                        float vmax = -INFINITY;
                        #pragma unroll
                        for (int nt = 0; nt < 4; nt++){
                            #pragma unroll
                            for (int j = 0; j < 2; j++){
                                float sq = fmaf(acc[mt][nt][h*2 + j], -2.f, qs[mt][h] + kq[nt*2 + j]);
                                float lv = -sqrta(fmaxf(sq, 0.f)) * C_L2T;
                                v[nt*2 + j] = lv;
                                vmax = fmaxf(vmax, lv);
                            }
                        }
                        if (has_diag){
                            #pragma unroll
                            for (int nt = 0; nt < 4; nt++)
                                #pragma unroll
                                for (int j = 0; j < 2; j++)
                                    if (nt*8 + 2*t + j == mt*16 + g + 8*h)
                                        g_pd[m0 + rloc] = v[nt*2 + j];
                        }
                        float s = 0.f;
                        #pragma unroll
                        for (int i2 = 0; i2 < 8; i2++) s += ex2a(v[i2] - vmax);
                        float nm = fmaxf(mrun[mt][h], vmax);
                        srun[mt][h] = srun[mt][h] * ex2a(fmaxf(mrun[mt][h] - nm, -126.f))
                                    + s * ex2a(vmax - nm);
                        mrun[mt][h] = nm;
                    }
                }
            }
            __syncthreads();   // rotate acc ring / align producer-consumer
        }

        // ---- segment flush (epilogue warps): t-lane merge, cross-cwp merge, store slot ----
        if (!is_mma){
            #pragma unroll
            for (int mt = 0; mt < 2; mt++){
                #pragma unroll
                for (int h = 0; h < 2; h++){
                    float m = mrun[mt][h], s = srun[mt][h];
                    #pragma unroll
                    for (int o = 1; o <= 2; o <<= 1){
                        float mo = __shfl_xor_sync(0xffffffffu, m, o);
                        float so = __shfl_xor_sync(0xffffffffu, s, o);
                        float nm = fmaxf(m, mo);
                        s = s * ex2a(fmaxf(m - nm, -126.f)) + so * ex2a(fmaxf(mo - nm, -126.f));
                        m = nm;
                    }
                    if (t == 0) part[cwp*128 + rw*32 + mt*16 + g + 8*h] = make_float2(m, s);
                }
            }
        }
        __syncthreads();
        if (!is_mma && cwp == 0){
            const int rl = rw*32 + lane;
            float2 p0 = part[0*128 + rl];
            float2 p1 = part[1*128 + rl];
            float m = fmaxf(p0.x, p1.x);
            float s = p0.y * ex2a(fmaxf(p0.x - m, -126.f)) + p1.y * ex2a(fmaxf(p1.x - m, -126.f));
            g_pm[(m0 + rl)*16 + cb_start] = m;
            g_ps[(m0 + rl)*16 + cb_start] = s;
        }

        if (havenext){ CP_WAIT0; __syncthreads(); buf ^= 1; }
        wi = seg_end;
    }
}

// ---------------- 5a: per-row loss + per-block partial sum (64 blocks) ----------------
__global__ void fin1_kernel(){
    const int r = blockIdx.x * 128 + threadIdx.x;
    const float4* pm4 = reinterpret_cast<const float4*>(&g_pm[r*16]);
    const float4* ps4 = reinterpret_cast<const float4*>(&g_ps[r*16]);
    float m = -INFINITY;
    float4 pm[4], ps[4];
    #pragma unroll
    for (int i = 0; i < 4; i++){
        pm[i] = pm4[i]; ps[i] = ps4[i];
        m = fmaxf(m, fmaxf(fmaxf(pm[i].x, pm[i].y), fmaxf(pm[i].z, pm[i].w)));
    }
    float s = 0.f;
    #pragma unroll
    for (int i = 0; i < 4; i++){
        s += ps[i].x * ex2a(fmaxf(pm[i].x - m, -126.f));
        s += ps[i].y * ex2a(fmaxf(pm[i].y - m, -126.f));
        s += ps[i].z * ex2a(fmaxf(pm[i].z - m, -126.f));
        s += ps[i].w * ex2a(fmaxf(pm[i].w - m, -126.f));
    }
    float loss = LN2F * (m + __log2f(s) - g_pd[r]);
    #pragma unroll
    for (int o = 16; o; o >>= 1) loss += __shfl_xor_sync(0xffffffffu, loss, o);
    __shared__ float sw[4];
    if ((threadIdx.x & 31) == 0) sw[threadIdx.x >> 5] = loss;
    __syncthreads();
    if (threadIdx.x == 0) g_bsum[blockIdx.x] = sw[0] + sw[1] + sw[2] + sw[3];
}

// ---------------- 5b: final sum ----------------
__global__ void fin2_kernel(float* __restrict__ out){
    float v = (threadIdx.x < FINB) ? g_bsum[threadIdx.x] : 0.f;
    #pragma unroll
    for (int o = 16; o; o >>= 1) v += __shfl_xor_sync(0xffffffffu, v, o);
    __shared__ float sw[2];
    if ((threadIdx.x & 31) == 0) sw[threadIdx.x >> 5] = v;
    __syncthreads();
    if (threadIdx.x == 0) out[0] = (sw[0] + sw[1]) / (float)P;
}

extern "C" void kernel_launch(void* const* d_in, const int* in_sizes, int n_in,
                              void* d_out, int out_size){
    const float* f1  = (const float*)d_in[0];
    const float* f2  = (const float*)d_in[1];
    const void*  map = d_in[2];

    cudaFuncSetAttribute(nce_main_kernel,
                         cudaFuncAttributeMaxDynamicSharedMemorySize, SMEM_TOTAL);

    detect_kernel<<<1, 256>>>((const int*)map);        // launch 1
    prepQ_kernel<<<P, 128>>>(f1, f2, map);             // launch 2
    prepKf_kernel<<<256, 256>>>(f2);                   // launch 3
    nce_main_kernel<<<NCTA, 512, SMEM_TOTAL>>>();      // launch 4 (ncu target)
    fin1_kernel<<<FINB, 128>>>();                      // launch 5
    fin2_kernel<<<1, 64>>>((float*)d_out);             // launch 6
}

// round 15
// speedup vs baseline: 1.0027x; 1.0027x over previous
#include <cuda_runtime.h>
#include <cuda_bf16.h>
#include <stdint.h>
#include <math.h>

#define P 8192
#define D 256
#define C_L2T 20.60992915555662f   // log2(e)/0.07
#define LN2F  0.6931471805599453f
#define NCTA 148
#define NITEMS 1024                // 64 row-tiles x 16 chunk-blocks (512 keys each)
#define FINB 64

// ---------------- device scratch (allocation-free) ----------------
__device__ int g_is64;
__device__ __align__(16) uint32_t g_Qh[P * 128];          // bf16x2 packed rows
// K in mma-B-fragment order: [kb(256)][kt(16)][u4(2)][lane(32)][4 u32] + pad
__device__ __align__(16) uint32_t g_Kf[256 * 4096 + 512];
// ksq in C-fragment order: [kb(256)][lane(32)][8 floats]
__device__ __align__(16) float g_ksqf[256 * 256];
__device__ float g_qsq[P];
__device__ float g_ksq[P];
__device__ __align__(16) float g_pm[P * 16];   // per-row, per-segment partial max
__device__ __align__(16) float g_ps[P * 16];   // partial sum
__device__ float g_pd[P];
__device__ float g_bsum[FINB];

// ---------------- smem: 2 Q buffers (128 rows x 528B each) + combine scratch ----------------
#define QBUF_BYTES 67584
#define OFF_PART   135168          // float2[4][128] = 4096B
#define SMEM_TOTAL 139264

// ---------------- PTX helpers (base-PTX only, sm_103-safe) ----------------
__device__ __forceinline__ uint32_t smem_u32(const void* p){
    uint32_t a;
    asm("{ .reg .u64 t; cvta.to.shared.u64 t, %1; cvt.u32.u64 %0, t; }" : "=r"(a) : "l"(p));
    return a;
}
__device__ __forceinline__ void cpa16(uint32_t dst, const void* src){
    asm volatile("cp.async.cg.shared.global [%0], [%1], 16;" :: "r"(dst), "l"(src));
}
#define CP_COMMIT asm volatile("cp.async.commit_group;" ::: "memory")
#define CP_WAIT0  asm volatile("cp.async.wait_group 0;" ::: "memory")

__device__ __forceinline__ void ldm_x4(uint32_t& r0, uint32_t& r1, uint32_t& r2, uint32_t& r3,
                                       uint32_t addr){
    asm volatile("ldmatrix.sync.aligned.m8n8.x4.shared.b16 {%0,%1,%2,%3}, [%4];"
                 : "=r"(r0), "=r"(r1), "=r"(r2), "=r"(r3) : "r"(addr));
}
__device__ __forceinline__ void mma_bf16(float c[4], const uint32_t a[4],
                                         uint32_t b0, uint32_t b1){
    asm volatile(
        "mma.sync.aligned.m16n8k16.row.col.f32.bf16.bf16.f32 "
        "{%0,%1,%2,%3}, {%4,%5,%6,%7}, {%8,%9}, {%0,%1,%2,%3};"
        : "+f"(c[0]), "+f"(c[1]), "+f"(c[2]), "+f"(c[3])
        : "r"(a[0]), "r"(a[1]), "r"(a[2]), "r"(a[3]), "r"(b0), "r"(b1));
}
__device__ __forceinline__ float ex2a(float x){ float y; asm("ex2.approx.f32 %0, %1;" : "=f"(y) : "f"(x)); return y; }
__device__ __forceinline__ float sqrta(float x){ float y; asm("sqrt.approx.f32 %0, %1;" : "=f"(y) : "f"(x)); return y; }
__device__ __forceinline__ uint32_t f2bf_bits(float x){
    return (uint32_t)__bfloat16_as_ushort(__float2bfloat16(x));
}

// ---------------- 1: dtype detection (int64 vs int32 map) ----------------
__global__ void detect_kernel(const int* __restrict__ m32){
    __shared__ int nz;
    if (threadIdx.x == 0) nz = 0;
    __syncthreads();
    int any = 0;
    for (int i = 1 + 2*(int)threadIdx.x; i < P; i += 2*(int)blockDim.x)
        if (m32[i] != 0) any = 1;
    if (any) atomicOr(&nz, 1);
    __syncthreads();
    if (threadIdx.x == 0) g_is64 = (nz == 0) ? 1 : 0;
}

// ---------------- 2: gather Q -> bf16 pack + qsq + ksq + partial-slot init ----------------
__global__ void prepQ_kernel(const float* __restrict__ f1, const float* __restrict__ f2,
                             const void* __restrict__ map){
    const int r = blockIdx.x, t = threadIdx.x;
    long long idx = g_is64 ? ((const long long*)map)[r]
                           : (long long)((const int*)map)[r];
    float2 q = reinterpret_cast<const float2*>(f1 + idx * (long long)D)[t];
    g_Qh[r*128 + t] = f2bf_bits(q.x) | (f2bf_bits(q.y) << 16);
    float2 k = reinterpret_cast<const float2*>(f2 + (long long)r * D)[t];
    if (t < 16){ g_pm[r*16 + t] = -INFINITY; g_ps[r*16 + t] = 0.f; }
    float qs = q.x*q.x + q.y*q.y;
    float ks = k.x*k.x + k.y*k.y;
    #pragma unroll
    for (int o = 16; o; o >>= 1){
        qs += __shfl_xor_sync(0xffffffffu, qs, o);
        ks += __shfl_xor_sync(0xffffffffu, ks, o);
    }
    __shared__ float sq[4], sk[4];
    if ((t & 31) == 0){ sq[t >> 5] = qs; sk[t >> 5] = ks; }
    __syncthreads();
    if (t == 0){
        g_qsq[r] = sq[0] + sq[1] + sq[2] + sq[3];
        g_ksq[r] = sk[0] + sk[1] + sk[2] + sk[3];
    }
}

// ---------------- 3: pack K into mma B-fragment layout + fragment-ordered ksq ----------------
// PTX m16n8k16 B fragment: lane L holds b0 = B[k=2(L%4)+{0,1}, n=L/4], b1 = same k+8.
__global__ void prepKf_kernel(const float* __restrict__ f2){
    const int kb = blockIdx.x;
    for (int idx = threadIdx.x; idx < 4096; idx += 256){
        int kt  = idx >> 8;
        int rem = idx & 255;
        int u4  = rem >> 7;
        int lam = (rem >> 2) & 31;
        int p   = rem & 3;
        int nt  = u4*2 + (p >> 1);
        int w   = p & 1;
        int n = kb*32 + nt*8 + (lam >> 2);
        int k = kt*16 + w*8 + (lam & 3)*2;
        const float* src = f2 + (long long)n * D + k;
        g_Kf[kb*4096 + idx] = f2bf_bits(src[0]) | (f2bf_bits(src[1]) << 16);
    }
    {
        int lam = threadIdx.x >> 3, i = threadIdx.x & 7;
        int nt = i >> 1, j = i & 1;
        g_ksqf[kb*256 + threadIdx.x] = g_ksq[kb*32 + nt*8 + (lam & 3)*2 + j];
    }
}

// ---------------- Q tile loader (cooperative, cp.async) ----------------
__device__ __forceinline__ void load_q_tile(uint32_t dstbase, int rt, int tid){
    const int m0 = rt << 7;
    for (int j = tid; j < 128*32; j += 512){
        int row = j >> 5, c2 = j & 31;
        cpa16(dstbase + (uint32_t)(row*528 + c2*16), &g_Qh[(size_t)(m0+row)*128 + c2*4]);
    }
}

// ---------------- epilogue for one 16-row x 32-key group ----------------
__device__ __forceinline__ void epi_group(
    const float (&ag)[4][4], const int hh, const float qsv,
    const float (&kqv)[8], const bool hd, const int dloc, const int tt,
    float* pd_addr, float& mr, float& sr)
{
    float v[8];
    float vmax = -INFINITY;
    #pragma unroll
    for (int nt = 0; nt < 4; nt++){
        #pragma unroll
        for (int j = 0; j < 2; j++){
            float sq = fmaf(ag[nt][hh*2 + j], -2.f, qsv + kqv[nt*2 + j]);
            float lv = -sqrta(fmaxf(sq, 0.f)) * C_L2T;
            v[nt*2 + j] = lv;
            vmax = fmaxf(vmax, lv);
        }
    }
    if (hd){
        #pragma unroll
        for (int nt = 0; nt < 4; nt++)
            #pragma unroll
            for (int j = 0; j < 2; j++)
                if (nt*8 + 2*tt + j == dloc) *pd_addr = v[nt*2 + j];
    }
    float s = 0.f;
    #pragma unroll
    for (int i = 0; i < 8; i++) s += ex2a(v[i] - vmax);
    float nm = fmaxf(mr, vmax);
    sr = sr * ex2a(fmaxf(mr - nm, -126.f)) + s * ex2a(vmax - nm);
    mr = nm;
}

// ---- one 32-key chunk: MMA of kb + interleaved epilogue of kbp (previous chunk) ----
// Epilogue groups of the previous chunk injected at kt = 3,7,11,15 so MUFU work
// overlaps HMMA within the SAME warp's instruction stream (no barriers, no smem).
__device__ __forceinline__ void chunk_body(
    const int kb, const int kbn, const int kbp, const bool do_epi,
    float (&accC)[2][4][4], float (&accP)[2][4][4],
    uint4 &blo, uint4 &bhi,
    const uint4* __restrict__ Bb,
    const uint32_t a_base,
    const float (&qs)[2][2],
    float (&mrun)[2][2], float (&srun)[2][2],
    const int diag_kb, const int m0, const int rw,
    const int g, const int t, const int lane)
{
    const uint4* bp  = Bb + (size_t)kb*1024 + lane;
    const uint4* npc = Bb + (size_t)kbn*1024 + lane;
    const bool hd = do_epi && (kbp == diag_kb);

    #pragma unroll
    for (int mt = 0; mt < 2; mt++)
        #pragma unroll
        for (int nt = 0; nt < 4; nt++)
            #pragma unroll
            for (int q4 = 0; q4 < 4; q4++) accC[mt][nt][q4] = 0.f;

    float kqP[8];
    #pragma unroll
    for (int kt = 0; kt < 16; kt++){
        uint4 clo = blo, chi = bhi;
        const uint4* np = (kt < 15) ? (bp + (kt + 1)*64) : npc;
        blo = __ldg(np); bhi = __ldg(np + 32);
        if (kt == 1 && do_epi){   // prev chunk's ksq fragment, used from kt=3 on
            const float4* kp = reinterpret_cast<const float4*>(g_ksqf)
                             + (size_t)kbp*64 + lane*2;
            float4 k0 = __ldg(kp), k1 = __ldg(kp + 1);
            kqP[0]=k0.x; kqP[1]=k0.y; kqP[2]=k0.z; kqP[3]=k0.w;
            kqP[4]=k1.x; kqP[5]=k1.y; kqP[6]=k1.z; kqP[7]=k1.w;
        }
        uint32_t A0[4], A1[4];
        ldm_x4(A0[0], A0[1], A0[2], A0[3], a_base + (uint32_t)(kt*32));
        ldm_x4(A1[0], A1[1], A1[2], A1[3], a_base + (uint32_t)(16*528 + kt*32));
        mma_bf16(accC[0][0], A0, clo.x, clo.y);
        mma_bf16(accC[0][1], A0, clo.z, clo.w);
        mma_bf16(accC[0][2], A0, chi.x, chi.y);
        mma_bf16(accC[0][3], A0, chi.z, chi.w);
        mma_bf16(accC[1][0], A1, clo.x, clo.y);
        mma_bf16(accC[1][1], A1, clo.z, clo.w);
        mma_bf16(accC[1][2], A1, chi.x, chi.y);
        mma_bf16(accC[1][3], A1, chi.z, chi.w);
        if ((kt & 3) == 3 && do_epi){   // 4 groups: kt=3,7,11,15 -> (mt,h)
            const int mt = kt >> 3, h = (kt >> 2) & 1;
            const int rloc = rw*32 + mt*16 + g + 8*h;
            epi_group(accP[mt], h, qs[mt][h], kqP, hd, mt*16 + g + 8*h, t,
                      &g_pd[m0 + rloc], mrun[mt][h], srun[mt][h]);
        }
    }
}

// ---------------- 4: main HMMA kernel — persistent, 148 CTAs ----------------
// 512 threads = 16 warps (4 rw x 4 cw); warp tile 32 rows x 32 keys.
// Software-pipelined: MMA of chunk c overlaps epilogue of chunk c-1 intra-warp.
__global__ void __launch_bounds__(512, 1) nce_main_kernel(){
    extern __shared__ __align__(16) uint8_t sm[];
    const uint32_t sb = smem_u32(sm);
    const int tid = threadIdx.x;
    const int lane = tid & 31, wid = tid >> 5;
    const int rw = wid >> 2, cw = wid & 3;
    const int g = lane >> 2, t = lane & 3;
    const int bid = blockIdx.x;

    int wi = (bid * NITEMS) / NCTA;
    const int we = ((bid + 1) * NITEMS) / NCTA;

    const uint32_t a_off = (uint32_t)((rw*32 + (lane & 15))*528 + (lane >> 4)*16);
    const uint4* Bb = reinterpret_cast<const uint4*>(g_Kf);
    float2* part = (float2*)(sm + OFF_PART);

    int buf = 0;
    load_q_tile(sb, wi >> 4, tid);
    CP_COMMIT; CP_WAIT0;
    __syncthreads();

    while (wi < we){
        const int rt = wi >> 4;
        const int cb_start = wi & 15;
        int seg_end = (rt + 1) << 4;
        if (seg_end > we) seg_end = we;
        const int ncb = seg_end - wi;
        const int nch = ncb * 4;            // 32-key chunks this warp sweeps
        const bool havenext = (seg_end < we);
        if (havenext){ load_q_tile(sb + (uint32_t)(buf^1)*QBUF_BYTES, seg_end >> 4, tid); CP_COMMIT; }

        const int m0 = rt << 7;
        const int diag_kb = rt*4 + rw;
        const uint32_t a_base = sb + (uint32_t)buf*QBUF_BYTES + a_off;

        // chunk index -> kb: kb(ci) = (cb_start + ci/4)*16 + cw*4 + (ci&3)
        #define KB_OF(ci) (((cb_start + ((ci) >> 2)) << 4) + (cw << 2) + ((ci) & 3))

        float qs[2][2];
        #pragma unroll
        for (int mt = 0; mt < 2; mt++){
            qs[mt][0] = g_qsq[m0 + rw*32 + mt*16 + g];
            qs[mt][1] = g_qsq[m0 + rw*32 + mt*16 + g + 8];
        }

        float mrun[2][2], srun[2][2];
        #pragma unroll
        for (int mt = 0; mt < 2; mt++)
            #pragma unroll
            for (int h = 0; h < 2; h++){ mrun[mt][h] = -INFINITY; srun[mt][h] = 0.f; }

        // prime B (kt0 of chunk 0)
        uint4 blo, bhi;
        {
            const uint4* p0 = Bb + (size_t)KB_OF(0)*1024 + lane;
            blo = __ldg(p0); bhi = __ldg(p0 + 32);
        }

        float accA[2][4][4], accB[2][4][4];
        for (int ci = 0; ci < nch; ci += 2){
            chunk_body(KB_OF(ci),   KB_OF(ci+1),
                       (ci > 0) ? KB_OF(ci-1) : 0, ci > 0,
                       accA, accB, blo, bhi, Bb, a_base, qs, mrun, srun,
                       diag_kb, m0, rw, g, t, lane);
            chunk_body(KB_OF(ci+1), (ci+2 < nch) ? KB_OF(ci+2) : KB_OF(ci+1),
                       KB_OF(ci), true,
                       accB, accA, blo, bhi, Bb, a_base, qs, mrun, srun,
                       diag_kb, m0, rw, g, t, lane);
        }
        // tail: epilogue of chunk nch-1 (in accB)
        {
            const int kbp = KB_OF(nch-1);
            const float4* kp = reinterpret_cast<const float4*>(g_ksqf)
                             + (size_t)kbp*64 + lane*2;
            float4 k0 = __ldg(kp), k1 = __ldg(kp + 1);
            float kqP[8] = {k0.x, k0.y, k0.z, k0.w, k1.x, k1.y, k1.z, k1.w};
            const bool hd = (kbp == diag_kb);
            #pragma unroll
            for (int mt = 0; mt < 2; mt++){
                #pragma unroll
                for (int h = 0; h < 2; h++){
                    const int rloc = rw*32 + mt*16 + g + 8*h;
                    epi_group(accB[mt], h, qs[mt][h], kqP, hd, mt*16 + g + 8*h, t,
                              &g_pd[m0 + rloc], mrun[mt][h], srun[mt][h]);
                }
            }
        }
        #undef KB_OF

        // ---- segment flush: t-lane merge, then cross-cw merge, store to slot cb_start ----
        __syncthreads();   // protect part[] from previous flush's readers
        #pragma unroll
        for (int mt = 0; mt < 2; mt++){
            #pragma unroll
            for (int h = 0; h < 2; h++){
                float m = mrun[mt][h], s = srun[mt][h];
                #pragma unroll
                for (int o = 1; o <= 2; o <<= 1){
                    float mo = __shfl_xor_sync(0xffffffffu, m, o);
                    float so = __shfl_xor_sync(0xffffffffu, s, o);
                    float nm = fmaxf(m, mo);
                    s = s * ex2a(fmaxf(m - nm, -126.f)) + so * ex2a(fmaxf(mo - nm, -126.f));
                    m = nm;
                }
                if (t == 0) part[cw*128 + rw*32 + mt*16 + g + 8*h] = make_float2(m, s);
            }
        }
        __syncthreads();
        if (cw == 0){
            const int rl = rw*32 + lane;
            float2 p0 = part[0*128 + rl];
            float2 p1 = part[1*128 + rl];
            float2 p2 = part[2*128 + rl];
            float2 p3 = part[3*128 + rl];
            float m = fmaxf(fmaxf(p0.x, p1.x), fmaxf(p2.x, p3.x));
            float s = p0.y * ex2a(fmaxf(p0.x - m, -126.f)) + p1.y * ex2a(fmaxf(p1.x - m, -126.f))
                    + p2.y * ex2a(fmaxf(p2.x - m, -126.f)) + p3.y * ex2a(fmaxf(p3.x - m, -126.f));
            g_pm[(m0 + rl)*16 + cb_start] = m;
            g_ps[(m0 + rl)*16 + cb_start] = s;
        }

        if (havenext){ CP_WAIT0; __syncthreads(); buf ^= 1; }
        wi = seg_end;
    }
}

// ---------------- 5a: per-row loss + per-block partial sum (64 blocks) ----------------
__global__ void fin1_kernel(){
    const int r = blockIdx.x * 128 + threadIdx.x;
    const float4* pm4 = reinterpret_cast<const float4*>(&g_pm[r*16]);
    const float4* ps4 = reinterpret_cast<const float4*>(&g_ps[r*16]);
    float m = -INFINITY;
    float4 pm[4], ps[4];
    #pragma unroll
    for (int i = 0; i < 4; i++){
        pm[i] = pm4[i]; ps[i] = ps4[i];
        m = fmaxf(m, fmaxf(fmaxf(pm[i].x, pm[i].y), fmaxf(pm[i].z, pm[i].w)));
    }
    float s = 0.f;
    #pragma unroll
    for (int i = 0; i < 4; i++){
        s += ps[i].x * ex2a(fmaxf(pm[i].x - m, -126.f));
        s += ps[i].y * ex2a(fmaxf(pm[i].y - m, -126.f));
        s += ps[i].z * ex2a(fmaxf(pm[i].z - m, -126.f));
        s += ps[i].w * ex2a(fmaxf(pm[i].w - m, -126.f));
    }
    float loss = LN2F * (m + __log2f(s) - g_pd[r]);
    #pragma unroll
    for (int o = 16; o; o >>= 1) loss += __shfl_xor_sync(0xffffffffu, loss, o);
    __shared__ float sw[4];
    if ((threadIdx.x & 31) == 0) sw[threadIdx.x >> 5] = loss;
    __syncthreads();
    if (threadIdx.x == 0) g_bsum[blockIdx.x] = sw[0] + sw[1] + sw[2] + sw[3];
}

// ---------------- 5b: final sum ----------------
__global__ void fin2_kernel(float* __restrict__ out){
    float v = (threadIdx.x < FINB) ? g_bsum[threadIdx.x] : 0.f;
    #pragma unroll
    for (int o = 16; o; o >>= 1) v += __shfl_xor_sync(0xffffffffu, v, o);
    __shared__ float sw[2];
    if ((threadIdx.x & 31) == 0) sw[threadIdx.x >> 5] = v;
    __syncthreads();
    if (threadIdx.x == 0) out[0] = (sw[0] + sw[1]) / (float)P;
}

extern "C" void kernel_launch(void* const* d_in, const int* in_sizes, int n_in,
                              void* d_out, int out_size){
    const float* f1  = (const float*)d_in[0];
    const float* f2  = (const float*)d_in[1];
    const void*  map = d_in[2];

    cudaFuncSetAttribute(nce_main_kernel,
                         cudaFuncAttributeMaxDynamicSharedMemorySize, SMEM_TOTAL);

    detect_kernel<<<1, 256>>>((const int*)map);        // launch 1
    prepQ_kernel<<<P, 128>>>(f1, f2, map);             // launch 2
    prepKf_kernel<<<256, 256>>>(f2);                   // launch 3
    nce_main_kernel<<<NCTA, 512, SMEM_TOTAL>>>();      // launch 4 (ncu target)
    fin1_kernel<<<FINB, 128>>>();                      // launch 5
    fin2_kernel<<<1, 64>>>((float*)d_out);             // launch 6
}

// round 16
// speedup vs baseline: 1.0136x; 1.0108x over previous
#include <cuda_runtime.h>
#include <cuda_bf16.h>
#include <stdint.h>
#include <math.h>

#define P 8192
#define D 256
#define C_L2T 20.60992915555662f   // log2(e)/0.07
#define LN2F  0.6931471805599453f
#define NCTA 148
#define NITEMS 1024                // 64 row-tiles x 16 chunk-blocks (512 keys each)
#define FINB 64

// ---------------- device scratch (allocation-free) ----------------
__device__ int g_is64;
__device__ __align__(16) uint32_t g_Qh[P * 128];          // bf16x2 packed rows
// K in mma-B-fragment order: [kb(256)][kt(16)][u4(2)][lane(32)][4 u32] + pad
__device__ __align__(16) uint32_t g_Kf[256 * 4096 + 512];
// ksq in C-fragment order: [kb(256)][lane(32)][8 floats]
__device__ __align__(16) float g_ksqf[256 * 256];
__device__ float g_qsq[P];
__device__ float g_ksq[P];
__device__ __align__(16) float g_pm[P * 16];   // per-row, per-segment partial max
__device__ __align__(16) float g_ps[P * 16];   // partial sum
__device__ float g_pd[P];
__device__ float g_bsum[FINB];

// ---------------- smem layout ----------------
// [0, 67584)        Q buf 0 (128 rows x 528B)
// [67584, 135168)   Q buf 1
// [135168, 200704)  acc ring: 2 slots x 32768 B (8 warps x 4096)
// [200704, 202752)  part: float2[2][128]
#define QBUF_BYTES 67584
#define OFF_ACC    135168
#define ACC_SLOT   32768
#define OFF_PART   200704
#define SMEM_TOTAL 202752

// ---------------- PTX helpers (base-PTX only, sm_103-safe) ----------------
__device__ __forceinline__ uint32_t smem_u32(const void* p){
    uint32_t a;
    asm("{ .reg .u64 t; cvta.to.shared.u64 t, %1; cvt.u32.u64 %0, t; }" : "=r"(a) : "l"(p));
    return a;
}
__device__ __forceinline__ void cpa16(uint32_t dst, const void* src){
    asm volatile("cp.async.cg.shared.global [%0], [%1], 16;" :: "r"(dst), "l"(src));
}
#define CP_COMMIT asm volatile("cp.async.commit_group;" ::: "memory")
#define CP_WAIT0  asm volatile("cp.async.wait_group 0;" ::: "memory")
#define PAIR_BAR(id) asm volatile("bar.sync %0, 64;" :: "r"(id) : "memory")

__device__ __forceinline__ void ldm_x4(uint32_t& r0, uint32_t& r1, uint32_t& r2, uint32_t& r3,
                                       uint32_t addr){
    asm volatile("ldmatrix.sync.aligned.m8n8.x4.shared.b16 {%0,%1,%2,%3}, [%4];"
                 : "=r"(r0), "=r"(r1), "=r"(r2), "=r"(r3) : "r"(addr));
}
__device__ __forceinline__ void mma_bf16(float c[4], const uint32_t a[4],
                                         uint32_t b0, uint32_t b1){
    asm volatile(
        "mma.sync.aligned.m16n8k16.row.col.f32.bf16.bf16.f32 "
        "{%0,%1,%2,%3}, {%4,%5,%6,%7}, {%8,%9}, {%0,%1,%2,%3};"
        : "+f"(c[0]), "+f"(c[1]), "+f"(c[2]), "+f"(c[3])
        : "r"(a[0]), "r"(a[1]), "r"(a[2]), "r"(a[3]), "r"(b0), "r"(b1));
}
__device__ __forceinline__ float ex2a(float x){ float y; asm("ex2.approx.f32 %0, %1;" : "=f"(y) : "f"(x)); return y; }
__device__ __forceinline__ float sqrta(float x){ float y; asm("sqrt.approx.f32 %0, %1;" : "=f"(y) : "f"(x)); return y; }
__device__ __forceinline__ uint32_t f2bf_bits(float x){
    return (uint32_t)__bfloat16_as_ushort(__float2bfloat16(x));
}

// ---------------- 1: dtype detection (int64 vs int32 map) ----------------
__global__ void detect_kernel(const int* __restrict__ m32){
    __shared__ int nz;
    if (threadIdx.x == 0) nz = 0;
    __syncthreads();
    int any = 0;
    for (int i = 1 + 2*(int)threadIdx.x; i < P; i += 2*(int)blockDim.x)
        if (m32[i] != 0) any = 1;
    if (any) atomicOr(&nz, 1);
    __syncthreads();
    if (threadIdx.x == 0) g_is64 = (nz == 0) ? 1 : 0;
}

// ---------------- 2: gather Q -> bf16 pack + qsq + ksq + partial-slot init ----------------
__global__ void prepQ_kernel(const float* __restrict__ f1, const float* __restrict__ f2,
                             const void* __restrict__ map){
    const int r = blockIdx.x, t = threadIdx.x;
    long long idx = g_is64 ? ((const long long*)map)[r]
                           : (long long)((const int*)map)[r];
    float2 q = reinterpret_cast<const float2*>(f1 + idx * (long long)D)[t];
    g_Qh[r*128 + t] = f2bf_bits(q.x) | (f2bf_bits(q.y) << 16);
    float2 k = reinterpret_cast<const float2*>(f2 + (long long)r * D)[t];
    if (t < 16){ g_pm[r*16 + t] = -INFINITY; g_ps[r*16 + t] = 0.f; }
    float qs = q.x*q.x + q.y*q.y;
    float ks = k.x*k.x + k.y*k.y;
    #pragma unroll
    for (int o = 16; o; o >>= 1){
        qs += __shfl_xor_sync(0xffffffffu, qs, o);
        ks += __shfl_xor_sync(0xffffffffu, ks, o);
    }
    __shared__ float sq[4], sk[4];
    if ((t & 31) == 0){ sq[t >> 5] = qs; sk[t >> 5] = ks; }
    __syncthreads();
    if (t == 0){
        g_qsq[r] = sq[0] + sq[1] + sq[2] + sq[3];
        g_ksq[r] = sk[0] + sk[1] + sk[2] + sk[3];
    }
}

// ---------------- 3: pack K into mma B-fragment layout + fragment-ordered ksq ----------------
__global__ void prepKf_kernel(const float* __restrict__ f2){
    const int kb = blockIdx.x;
    for (int idx = threadIdx.x; idx < 4096; idx += 256){
        int kt  = idx >> 8;
        int rem = idx & 255;
        int u4  = rem >> 7;
        int lam = (rem >> 2) & 31;
        int p   = rem & 3;
        int nt  = u4*2 + (p >> 1);
        int w   = p & 1;
        int n = kb*32 + nt*8 + (lam >> 2);
        int k = kt*16 + w*8 + (lam & 3)*2;
        const float* src = f2 + (long long)n * D + k;
        g_Kf[kb*4096 + idx] = f2bf_bits(src[0]) | (f2bf_bits(src[1]) << 16);
    }
    {
        int lam = threadIdx.x >> 3, i = threadIdx.x & 7;
        int nt = i >> 1, j = i & 1;
        g_ksqf[kb*256 + threadIdx.x] = g_ksq[kb*32 + nt*8 + (lam & 3)*2 + j];
    }
}

// ---------------- Q tile loader (cooperative, cp.async) ----------------
__device__ __forceinline__ void load_q_tile(uint32_t dstbase, int rt, int tid){
    const int m0 = rt << 7;
    for (int j = tid; j < 128*32; j += 512){
        int row = j >> 5, c2 = j & 31;
        cpa16(dstbase + (uint32_t)(row*528 + c2*16), &g_Qh[(size_t)(m0+row)*128 + c2*4]);
    }
}

// ---------------- 4: main kernel — warp-specialized, pairwise named barriers ----------------
// 148 persistent CTAs, 512 threads = 16 warps.
// MMA warp w (0-7) pairs with epilogue warp w+8 via named barrier (1+w), count 64.
// 2-slot acc ring per pair; rendezvous at chunk c = "slot c full AND slot c-1 drained",
// so producer runs chunk c+1 while consumer runs chunk c. No CTA barrier in the loop:
// the 8 pairs free-run, keeping the tensor pipe continuously fed while MUFU runs
// concurrently on the consumer warps.
__global__ void __launch_bounds__(512, 1) nce_main_kernel(){
    extern __shared__ __align__(16) uint8_t sm[];
    const uint32_t sb = smem_u32(sm);
    const int tid = threadIdx.x;
    const int lane = tid & 31, wid = tid >> 5;
    const bool is_mma = (wid < 8);
    const int e  = wid & 7;            // role-local warp index / pair id
    const int rw = e >> 1, cwp = e & 1;
    const int g = lane >> 2, t = lane & 3;
    const int bid = blockIdx.x;

    int wi = (bid * NITEMS) / NCTA;
    const int we = ((bid + 1) * NITEMS) / NCTA;

    const uint32_t a_off = (uint32_t)((rw*32 + (lane & 15))*528 + (lane >> 4)*16);
    const uint4*  Bb = reinterpret_cast<const uint4*>(g_Kf);
    const float4* Kb = reinterpret_cast<const float4*>(g_ksqf);
    float2* part = (float2*)(sm + OFF_PART);
    float4* accw0 = (float4*)(sm + OFF_ACC + e*4096);
    float4* accw1 = (float4*)(sm + OFF_ACC + ACC_SLOT + e*4096);

    int buf = 0;
    load_q_tile(sb, wi >> 4, tid);
    CP_COMMIT; CP_WAIT0;
    __syncthreads();

    while (wi < we){
        const int rt = wi >> 4;
        const int cb_start = wi & 15;
        int seg_end = (rt + 1) << 4;
        if (seg_end > we) seg_end = we;
        const int ncb = seg_end - wi;
        const int nch = ncb * 8;            // 64-key chunks in this segment
        const bool havenext = (seg_end < we);
        if (havenext){ load_q_tile(sb + (uint32_t)(buf^1)*QBUF_BYTES, seg_end >> 4, tid); CP_COMMIT; }

        const int m0 = rt << 7;
        const int kbase = cb_start * 16;    // first 32-key block of segment
        const int diag_kb = rt*4 + rw;
        const uint32_t a_base = sb + (uint32_t)buf*QBUF_BYTES + a_off;

        if (is_mma){
            // ---------------- producer loop ----------------
            uint4 blo[2], bhi[2];
            {
                const uint4* p0 = Bb + (size_t)(kbase + cwp)*1024 + lane;
                blo[0] = __ldg(p0);      bhi[0] = __ldg(p0 + 32);
                blo[1] = __ldg(p0 + 64); bhi[1] = __ldg(p0 + 96);
            }
            for (int cc = 0; cc < nch; cc++){
                const int kb  = kbase + cc*2 + cwp;
                const int kbn = kbase + ((cc + 1 < nch) ? (cc + 1) : cc)*2 + cwp;
                const uint4* bp  = Bb + (size_t)kb*1024 + lane;
                const uint4* npc = Bb + (size_t)kbn*1024 + lane;

                float acc[2][4][4];
                #pragma unroll
                for (int mt = 0; mt < 2; mt++)
                    #pragma unroll
                    for (int nt = 0; nt < 4; nt++)
                        #pragma unroll
                        for (int q4 = 0; q4 < 4; q4++) acc[mt][nt][q4] = 0.f;

                #pragma unroll
                for (int kt = 0; kt < 16; kt++){
                    uint4 clo = blo[kt & 1], chi = bhi[kt & 1];
                    const uint4* np = (kt < 14) ? (bp + (kt + 2)*64) : (npc + (kt - 14)*64);
                    blo[kt & 1] = __ldg(np); bhi[kt & 1] = __ldg(np + 32);
                    uint32_t A0[4], A1[4];
                    ldm_x4(A0[0], A0[1], A0[2], A0[3], a_base + (uint32_t)(kt*32));
                    ldm_x4(A1[0], A1[1], A1[2], A1[3], a_base + (uint32_t)(16*528 + kt*32));
                    mma_bf16(acc[0][0], A0, clo.x, clo.y);
                    mma_bf16(acc[0][1], A0, clo.z, clo.w);
                    mma_bf16(acc[0][2], A0, chi.x, chi.y);
                    mma_bf16(acc[0][3], A0, chi.z, chi.w);
                    mma_bf16(acc[1][0], A1, clo.x, clo.y);
                    mma_bf16(acc[1][1], A1, clo.z, clo.w);
                    mma_bf16(acc[1][2], A1, chi.x, chi.y);
                    mma_bf16(acc[1][3], A1, chi.z, chi.w);
                }

                float4* dst = (cc & 1) ? accw1 : accw0;
                #pragma unroll
                for (int mt = 0; mt < 2; mt++)
                    #pragma unroll
                    for (int nt = 0; nt < 4; nt++)
                        dst[(mt*4 + nt)*32 + lane] =
                            make_float4(acc[mt][nt][0], acc[mt][nt][1],
                                        acc[mt][nt][2], acc[mt][nt][3]);
                PAIR_BAR(1 + e);   // rendezvous cc: slot cc full, slot cc-1 drained
            }
        } else {
            // ---------------- consumer loop ----------------
            float qs[2][2], mrun[2][2], srun[2][2];
            #pragma unroll
            for (int mt = 0; mt < 2; mt++){
                qs[mt][0] = g_qsq[m0 + rw*32 + mt*16 + g];
                qs[mt][1] = g_qsq[m0 + rw*32 + mt*16 + g + 8];
                mrun[mt][0] = mrun[mt][1] = -INFINITY;
                srun[mt][0] = srun[mt][1] = 0.f;
            }
            for (int cc = 0; cc < nch; cc++){
                PAIR_BAR(1 + e);   // wait for slot cc
                const int kbp = kbase + cc*2 + cwp;
                const float4* src = (cc & 1) ? accw1 : accw0;

                float acc[2][4][4];
                #pragma unroll
                for (int mt = 0; mt < 2; mt++)
                    #pragma unroll
                    for (int nt = 0; nt < 4; nt++){
                        float4 x = src[(mt*4 + nt)*32 + lane];
                        acc[mt][nt][0] = x.x; acc[mt][nt][1] = x.y;
                        acc[mt][nt][2] = x.z; acc[mt][nt][3] = x.w;
                    }

                const float4* kp = Kb + (size_t)kbp*64 + lane*2;
                float4 kq0 = __ldg(kp), kq1 = __ldg(kp + 1);
                float kq[8] = {kq0.x, kq0.y, kq0.z, kq0.w, kq1.x, kq1.y, kq1.z, kq1.w};
                const bool has_diag = (kbp == diag_kb);
                #pragma unroll
                for (int mt = 0; mt < 2; mt++){
                    #pragma unroll
                    for (int h = 0; h < 2; h++){
                        const int rloc = rw*32 + mt*16 + g + 8*h;
                        float v[8];
                        float vmax = -INFINITY;
                        #pragma unroll
                        for (int nt = 0; nt < 4; nt++){
                            #pragma unroll
                            for (int j = 0; j < 2; j++){
                                float sq = fmaf(acc[mt][nt][h*2 + j], -2.f, qs[mt][h] + kq[nt*2 + j]);
                                float lv = -sqrta(fmaxf(sq, 0.f)) * C_L2T;
                                v[nt*2 + j] = lv;
                                vmax = fmaxf(vmax, lv);
                            }
                        }
                        if (has_diag){
                            #pragma unroll
                            for (int nt = 0; nt < 4; nt++)
                                #pragma unroll
                                for (int j = 0; j < 2; j++)
                                    if (nt*8 + 2*t + j == mt*16 + g + 8*h)
                                        g_pd[m0 + rloc] = v[nt*2 + j];
                        }
                        float s = 0.f;
                        #pragma unroll
                        for (int i2 = 0; i2 < 8; i2++) s += ex2a(v[i2] - vmax);
                        float nm = fmaxf(mrun[mt][h], vmax);
                        srun[mt][h] = srun[mt][h] * ex2a(fmaxf(mrun[mt][h] - nm, -126.f))
                                    + s * ex2a(vmax - nm);
                        mrun[mt][h] = nm;
                    }
                }
            }
            // stage partials for flush (pre-CTA-barrier writes, read after barrier)
            #pragma unroll
            for (int mt = 0; mt < 2; mt++){
                #pragma unroll
                for (int h = 0; h < 2; h++){
                    float m = mrun[mt][h], s = srun[mt][h];
                    #pragma unroll
                    for (int o = 1; o <= 2; o <<= 1){
                        float mo = __shfl_xor_sync(0xffffffffu, m, o);
                        float so = __shfl_xor_sync(0xffffffffu, s, o);
                        float nm = fmaxf(m, mo);
                        s = s * ex2a(fmaxf(m - nm, -126.f)) + so * ex2a(fmaxf(mo - nm, -126.f));
                        m = nm;
                    }
                    if (t == 0) part[cwp*128 + rw*32 + mt*16 + g + 8*h] = make_float2(m, s);
                }
            }
        }

        __syncthreads();   // all pairs done; part[] visible
        if (!is_mma && cwp == 0){
            const int rl = rw*32 + lane;
            float2 p0 = part[0*128 + rl];
            float2 p1 = part[1*128 + rl];
            float m = fmaxf(p0.x, p1.x);
            float s = p0.y * ex2a(fmaxf(p0.x - m, -126.f)) + p1.y * ex2a(fmaxf(p1.x - m, -126.f));
            g_pm[(m0 + rl)*16 + cb_start] = m;
            g_ps[(m0 + rl)*16 + cb_start] = s;
        }

        if (havenext){ CP_WAIT0; __syncthreads(); buf ^= 1; }
        wi = seg_end;
    }
}

// ---------------- 5a: per-row loss + per-block partial sum (64 blocks) ----------------
__global__ void fin1_kernel(){
    const int r = blockIdx.x * 128 + threadIdx.x;
    const float4* pm4 = reinterpret_cast<const float4*>(&g_pm[r*16]);
    const float4* ps4 = reinterpret_cast<const float4*>(&g_ps[r*16]);
    float m = -INFINITY;
    float4 pm[4], ps[4];
    #pragma unroll
    for (int i = 0; i < 4; i++){
        pm[i] = pm4[i]; ps[i] = ps4[i];
        m = fmaxf(m, fmaxf(fmaxf(pm[i].x, pm[i].y), fmaxf(pm[i].z, pm[i].w)));
    }
    float s = 0.f;
    #pragma unroll
    for (int i = 0; i < 4; i++){
        s += ps[i].x * ex2a(fmaxf(pm[i].x - m, -126.f));
        s += ps[i].y * ex2a(fmaxf(pm[i].y - m, -126.f));
        s += ps[i].z * ex2a(fmaxf(pm[i].z - m, -126.f));
        s += ps[i].w * ex2a(fmaxf(pm[i].w - m, -126.f));
    }
    float loss = LN2F * (m + __log2f(s) - g_pd[r]);
    #pragma unroll
    for (int o = 16; o; o >>= 1) loss += __shfl_xor_sync(0xffffffffu, loss, o);
    __shared__ float sw[4];
    if ((threadIdx.x & 31) == 0) sw[threadIdx.x >> 5] = loss;
    __syncthreads();
    if (threadIdx.x == 0) g_bsum[blockIdx.x] = sw[0] + sw[1] + sw[2] + sw[3];
}

// ---------------- 5b: final sum ----------------
__global__ void fin2_kernel(float* __restrict__ out){
    float v = (threadIdx.x < FINB) ? g_bsum[threadIdx.x] : 0.f;
    #pragma unroll
    for (int o = 16; o; o >>= 1) v += __shfl_xor_sync(0xffffffffu, v, o);
    __shared__ float sw[2];
    if ((threadIdx.x & 31) == 0) sw[threadIdx.x >> 5] = v;
    __syncthreads();
    if (threadIdx.x == 0) out[0] = (sw[0] + sw[1]) / (float)P;
}

extern "C" void kernel_launch(void* const* d_in, const int* in_sizes, int n_in,
                              void* d_out, int out_size){
    const float* f1  = (const float*)d_in[0];
    const float* f2  = (const float*)d_in[1];
    const void*  map = d_in[2];

    cudaFuncSetAttribute(nce_main_kernel,
                         cudaFuncAttributeMaxDynamicSharedMemorySize, SMEM_TOTAL);

    detect_kernel<<<1, 256>>>((const int*)map);        // launch 1
    prepQ_kernel<<<P, 128>>>(f1, f2, map);             // launch 2
    prepKf_kernel<<<256, 256>>>(f2);                   // launch 3
    nce_main_kernel<<<NCTA, 512, SMEM_TOTAL>>>();      // launch 4 (ncu target)
    fin1_kernel<<<FINB, 128>>>();                      // launch 5
    fin2_kernel<<<1, 64>>>((float*)d_out);             // launch 6
}

// round 17
// speedup vs baseline: 1.0639x; 1.0497x over previous
#include <cuda_runtime.h>
#include <cuda_bf16.h>
#include <stdint.h>
#include <math.h>

#define P 8192
#define D 256
#define C_L2T 20.60992915555662f   // log2(e)/0.07
#define LN2F  0.6931471805599453f
#define NCTA 148
#define NITEMS 1024                // 64 row-tiles x 16 chunk-blocks (512 keys each)
#define FINB 64

// ---------------- device scratch (allocation-free) ----------------
__device__ int g_is64;
__device__ __align__(16) uint32_t g_Qh[P * 128];          // bf16x2 packed rows
// K in mma-B-fragment order: [kb(256)][kt(16)][u4(2)][lane(32)][4 u32] + pad
__device__ __align__(16) uint32_t g_Kf[256 * 4096 + 512];
// ksq in C-fragment order: [kb(256)][lane(32)][8 floats]
__device__ __align__(16) float g_ksqf[256 * 256];
__device__ float g_qsq[P];
__device__ float g_ksq[P];
__device__ __align__(16) float g_pm[P * 16];   // per-row, per-segment partial max
__device__ __align__(16) float g_ps[P * 16];   // partial sum
__device__ float g_pd[P];
__device__ float g_bsum[FINB];

// ---------------- smem layout ----------------
// [0, 67584)        Q buf 0 (128 rows x 528B)
// [67584, 135168)   Q buf 1
// [135168, 200704)  acc ring: 2 slots x 32768 B (8 warps x 4096)
// [200704, 202752)  part: float2[2][128]
#define QBUF_BYTES 67584
#define OFF_ACC    135168
#define ACC_SLOT   32768
#define OFF_PART   200704
#define SMEM_TOTAL 202752

// ---------------- PTX helpers (base-PTX only, sm_103-safe) ----------------
__device__ __forceinline__ uint32_t smem_u32(const void* p){
    uint32_t a;
    asm("{ .reg .u64 t; cvta.to.shared.u64 t, %1; cvt.u32.u64 %0, t; }" : "=r"(a) : "l"(p));
    return a;
}
__device__ __forceinline__ void cpa16(uint32_t dst, const void* src){
    asm volatile("cp.async.cg.shared.global [%0], [%1], 16;" :: "r"(dst), "l"(src));
}
#define CP_COMMIT asm volatile("cp.async.commit_group;" ::: "memory")
#define CP_WAIT0  asm volatile("cp.async.wait_group 0;" ::: "memory")
#define PAIR_BAR(id) asm volatile("bar.sync %0, 64;" :: "r"(id) : "memory")

__device__ __forceinline__ void ldm_x4(uint32_t& r0, uint32_t& r1, uint32_t& r2, uint32_t& r3,
                                       uint32_t addr){
    asm volatile("ldmatrix.sync.aligned.m8n8.x4.shared.b16 {%0,%1,%2,%3}, [%4];"
                 : "=r"(r0), "=r"(r1), "=r"(r2), "=r"(r3) : "r"(addr));
}
__device__ __forceinline__ void mma_bf16(float c[4], const uint32_t a[4],
                                         uint32_t b0, uint32_t b1){
    asm volatile(
        "mma.sync.aligned.m16n8k16.row.col.f32.bf16.bf16.f32 "
        "{%0,%1,%2,%3}, {%4,%5,%6,%7}, {%8,%9}, {%0,%1,%2,%3};"
        : "+f"(c[0]), "+f"(c[1]), "+f"(c[2]), "+f"(c[3])
        : "r"(a[0]), "r"(a[1]), "r"(a[2]), "r"(a[3]), "r"(b0), "r"(b1));
}
__device__ __forceinline__ float ex2a(float x){ float y; asm("ex2.approx.f32 %0, %1;" : "=f"(y) : "f"(x)); return y; }
__device__ __forceinline__ float sqrta(float x){ float y; asm("sqrt.approx.f32 %0, %1;" : "=f"(y) : "f"(x)); return y; }
__device__ __forceinline__ uint32_t f2bf_bits(float x){
    return (uint32_t)__bfloat16_as_ushort(__float2bfloat16(x));
}

// ---------------- 1: dtype detection (int64 vs int32 map) ----------------
__global__ void detect_kernel(const int* __restrict__ m32){
    __shared__ int nz;
    if (threadIdx.x == 0) nz = 0;
    __syncthreads();
    int any = 0;
    for (int i = 1 + 2*(int)threadIdx.x; i < P; i += 2*(int)blockDim.x)
        if (m32[i] != 0) any = 1;
    if (any) atomicOr(&nz, 1);
    __syncthreads();
    if (threadIdx.x == 0) g_is64 = (nz == 0) ? 1 : 0;
}

// ---------------- 2: gather Q -> bf16 pack + qsq + ksq + partial-slot init ----------------
__global__ void prepQ_kernel(const float* __restrict__ f1, const float* __restrict__ f2,
                             const void* __restrict__ map){
    const int r = blockIdx.x, t = threadIdx.x;
    long long idx = g_is64 ? ((const long long*)map)[r]
                           : (long long)((const int*)map)[r];
    float2 q = reinterpret_cast<const float2*>(f1 + idx * (long long)D)[t];
    g_Qh[r*128 + t] = f2bf_bits(q.x) | (f2bf_bits(q.y) << 16);
    float2 k = reinterpret_cast<const float2*>(f2 + (long long)r * D)[t];
    if (t < 16){ g_pm[r*16 + t] = -INFINITY; g_ps[r*16 + t] = 0.f; }
    float qs = q.x*q.x + q.y*q.y;
    float ks = k.x*k.x + k.y*k.y;
    #pragma unroll
    for (int o = 16; o; o >>= 1){
        qs += __shfl_xor_sync(0xffffffffu, qs, o);
        ks += __shfl_xor_sync(0xffffffffu, ks, o);
    }
    __shared__ float sq[4], sk[4];
    if ((t & 31) == 0){ sq[t >> 5] = qs; sk[t >> 5] = ks; }
    __syncthreads();
    if (t == 0){
        g_qsq[r] = sq[0] + sq[1] + sq[2] + sq[3];
        g_ksq[r] = sk[0] + sk[1] + sk[2] + sk[3];
    }
}

// ---------------- 3: pack K into mma B-fragment layout + fragment-ordered ksq ----------------
__global__ void prepKf_kernel(const float* __restrict__ f2){
    const int kb = blockIdx.x;
    for (int idx = threadIdx.x; idx < 4096; idx += 256){
        int kt  = idx >> 8;
        int rem = idx & 255;
        int u4  = rem >> 7;
        int lam = (rem >> 2) & 31;
        int p   = rem & 3;
        int nt  = u4*2 + (p >> 1);
        int w   = p & 1;
        int n = kb*32 + nt*8 + (lam >> 2);
        int k = kt*16 + w*8 + (lam & 3)*2;
        const float* src = f2 + (long long)n * D + k;
        g_Kf[kb*4096 + idx] = f2bf_bits(src[0]) | (f2bf_bits(src[1]) << 16);
    }
    {
        int lam = threadIdx.x >> 3, i = threadIdx.x & 7;
        int nt = i >> 1, j = i & 1;
        g_ksqf[kb*256 + threadIdx.x] = g_ksq[kb*32 + nt*8 + (lam & 3)*2 + j];
    }
}

// ---------------- Q tile loader (cooperative, cp.async) ----------------
__device__ __forceinline__ void load_q_tile(uint32_t dstbase, int rt, int tid){
    const int m0 = rt << 7;
    for (int j = tid; j < 128*32; j += 512){
        int row = j >> 5, c2 = j & 31;
        cpa16(dstbase + (uint32_t)(row*528 + c2*16), &g_Qh[(size_t)(m0+row)*128 + c2*4]);
    }
}

// ---------------- 4: main kernel — warp-specialized, pairwise named barriers,
//                    producer A-fragment prefetch (double-buffered LDSM) ----------------
// 148 persistent CTAs, 512 threads = 16 warps.
// MMA warp w (0-7) pairs with epilogue warp w+8 via named barrier (1+w), count 64.
// 2-slot acc ring per pair; rendezvous at chunk c = "slot c full AND slot c-1 drained".
// A fragments are chunk-invariant (Q tile fixed per segment), so the producer
// prefetches kt+1's A while HMMAs consume kt's A — LDSM latency hides under the
// tensor pipe; kt=15 wraps to kt0 which is byte-identical for the next chunk.
__global__ void __launch_bounds__(512, 1) nce_main_kernel(){
    extern __shared__ __align__(16) uint8_t sm[];
    const uint32_t sb = smem_u32(sm);
    const int tid = threadIdx.x;
    const int lane = tid & 31, wid = tid >> 5;
    const bool is_mma = (wid < 8);
    const int e  = wid & 7;            // role-local warp index / pair id
    const int rw = e >> 1, cwp = e & 1;
    const int g = lane >> 2, t = lane & 3;
    const int bid = blockIdx.x;

    int wi = (bid * NITEMS) / NCTA;
    const int we = ((bid + 1) * NITEMS) / NCTA;

    const uint32_t a_off = (uint32_t)((rw*32 + (lane & 15))*528 + (lane >> 4)*16);
    const uint4*  Bb = reinterpret_cast<const uint4*>(g_Kf);
    const float4* Kb = reinterpret_cast<const float4*>(g_ksqf);
    float2* part = (float2*)(sm + OFF_PART);
    float4* accw0 = (float4*)(sm + OFF_ACC + e*4096);
    float4* accw1 = (float4*)(sm + OFF_ACC + ACC_SLOT + e*4096);

    int buf = 0;
    load_q_tile(sb, wi >> 4, tid);
    CP_COMMIT; CP_WAIT0;
    __syncthreads();

    while (wi < we){
        const int rt = wi >> 4;
        const int cb_start = wi & 15;
        int seg_end = (rt + 1) << 4;
        if (seg_end > we) seg_end = we;
        const int ncb = seg_end - wi;
        const int nch = ncb * 8;            // 64-key chunks in this segment
        const bool havenext = (seg_end < we);
        if (havenext){ load_q_tile(sb + (uint32_t)(buf^1)*QBUF_BYTES, seg_end >> 4, tid); CP_COMMIT; }

        const int m0 = rt << 7;
        const int kbase = cb_start * 16;    // first 32-key block of segment
        const int diag_kb = rt*4 + rw;
        const uint32_t a_base = sb + (uint32_t)buf*QBUF_BYTES + a_off;

        if (is_mma){
            // ---------------- producer loop ----------------
            uint4 blo[2], bhi[2];
            {
                const uint4* p0 = Bb + (size_t)(kbase + cwp)*1024 + lane;
                blo[0] = __ldg(p0);      bhi[0] = __ldg(p0 + 32);
                blo[1] = __ldg(p0 + 64); bhi[1] = __ldg(p0 + 96);
            }
            // prime A fragments for kt=0 (chunk-invariant within segment)
            uint32_t A0[2][4], A1[2][4];
            ldm_x4(A0[0][0], A0[0][1], A0[0][2], A0[0][3], a_base);
            ldm_x4(A1[0][0], A1[0][1], A1[0][2], A1[0][3], a_base + (uint32_t)(16*528));

            for (int cc = 0; cc < nch; cc++){
                const int kb  = kbase + cc*2 + cwp;
                const int kbn = kbase + ((cc + 1 < nch) ? (cc + 1) : cc)*2 + cwp;
                const uint4* bp  = Bb + (size_t)kb*1024 + lane;
                const uint4* npc = Bb + (size_t)kbn*1024 + lane;

                float acc[2][4][4];
                #pragma unroll
                for (int mt = 0; mt < 2; mt++)
                    #pragma unroll
                    for (int nt = 0; nt < 4; nt++)
                        #pragma unroll
                        for (int q4 = 0; q4 < 4; q4++) acc[mt][nt][q4] = 0.f;

                #pragma unroll
                for (int kt = 0; kt < 16; kt++){
                    const int cur = kt & 1, nxt = cur ^ 1;
                    // prefetch A for kt+1 (kt=15 wraps to kt0: identical for next chunk)
                    const uint32_t ktn = (uint32_t)(((kt + 1) & 15) * 32);
                    ldm_x4(A0[nxt][0], A0[nxt][1], A0[nxt][2], A0[nxt][3],
                           a_base + ktn);
                    ldm_x4(A1[nxt][0], A1[nxt][1], A1[nxt][2], A1[nxt][3],
                           a_base + (uint32_t)(16*528) + ktn);
                    uint4 clo = blo[cur], chi = bhi[cur];
                    const uint4* np = (kt < 14) ? (bp + (kt + 2)*64) : (npc + (kt - 14)*64);
                    blo[cur] = __ldg(np); bhi[cur] = __ldg(np + 32);
                    mma_bf16(acc[0][0], A0[cur], clo.x, clo.y);
                    mma_bf16(acc[0][1], A0[cur], clo.z, clo.w);
                    mma_bf16(acc[0][2], A0[cur], chi.x, chi.y);
                    mma_bf16(acc[0][3], A0[cur], chi.z, chi.w);
                    mma_bf16(acc[1][0], A1[cur], clo.x, clo.y);
                    mma_bf16(acc[1][1], A1[cur], clo.z, clo.w);
                    mma_bf16(acc[1][2], A1[cur], chi.x, chi.y);
                    mma_bf16(acc[1][3], A1[cur], chi.z, chi.w);
                }

                float4* dst = (cc & 1) ? accw1 : accw0;
                #pragma unroll
                for (int mt = 0; mt < 2; mt++)
                    #pragma unroll
                    for (int nt = 0; nt < 4; nt++)
                        dst[(mt*4 + nt)*32 + lane] =
                            make_float4(acc[mt][nt][0], acc[mt][nt][1],
                                        acc[mt][nt][2], acc[mt][nt][3]);
                PAIR_BAR(1 + e);   // rendezvous cc: slot cc full, slot cc-1 drained
            }
        } else {
            // ---------------- consumer loop ----------------
            float qs[2][2], mrun[2][2], srun[2][2];
            #pragma unroll
            for (int mt = 0; mt < 2; mt++){
                qs[mt][0] = g_qsq[m0 + rw*32 + mt*16 + g];
                qs[mt][1] = g_qsq[m0 + rw*32 + mt*16 + g + 8];
                mrun[mt][0] = mrun[mt][1] = -INFINITY;
                srun[mt][0] = srun[mt][1] = 0.f;
            }
            for (int cc = 0; cc < nch; cc++){
                PAIR_BAR(1 + e);   // wait for slot cc
                const int kbp = kbase + cc*2 + cwp;
                const float4* src = (cc & 1) ? accw1 : accw0;

                float acc[2][4][4];
                #pragma unroll
                for (int mt = 0; mt < 2; mt++)
                    #pragma unroll
                    for (int nt = 0; nt < 4; nt++){
                        float4 x = src[(mt*4 + nt)*32 + lane];
                        acc[mt][nt][0] = x.x; acc[mt][nt][1] = x.y;
                        acc[mt][nt][2] = x.z; acc[mt][nt][3] = x.w;
                    }

                const float4* kp = Kb + (size_t)kbp*64 + lane*2;
                float4 kq0 = __ldg(kp), kq1 = __ldg(kp + 1);
                float kq[8] = {kq0.x, kq0.y, kq0.z, kq0.w, kq1.x, kq1.y, kq1.z, kq1.w};
                const bool has_diag = (kbp == diag_kb);
                #pragma unroll
                for (int mt = 0; mt < 2; mt++){
                    #pragma unroll
                    for (int h = 0; h < 2; h++){
                        const int rloc = rw*32 + mt*16 + g + 8*h;
                        float v[8];
                        float vmax = -INFINITY;
                        #pragma unroll
                        for (int nt = 0; nt < 4; nt++){
                            #pragma unroll
                            for (int j = 0; j < 2; j++){
                                float sq = fmaf(acc[mt][nt][h*2 + j], -2.f, qs[mt][h] + kq[nt*2 + j]);
                                float lv = -sqrta(fmaxf(sq, 0.f)) * C_L2T;
                                v[nt*2 + j] = lv;
                                vmax = fmaxf(vmax, lv);
                            }
                        }
                        if (has_diag){
                            #pragma unroll
                            for (int nt = 0; nt < 4; nt++)
                                #pragma unroll
                                for (int j = 0; j < 2; j++)
                                    if (nt*8 + 2*t + j == mt*16 + g + 8*h)
                                        g_pd[m0 + rloc] = v[nt*2 + j];
                        }
                        float s = 0.f;
                        #pragma unroll
                        for (int i2 = 0; i2 < 8; i2++) s += ex2a(v[i2] - vmax);
                        float nm = fmaxf(mrun[mt][h], vmax);
                        srun[mt][h] = srun[mt][h] * ex2a(fmaxf(mrun[mt][h] - nm, -126.f))
                                    + s * ex2a(vmax - nm);
                        mrun[mt][h] = nm;
                    }
                }
            }
            // stage partials for flush (pre-CTA-barrier writes, read after barrier)
            #pragma unroll
            for (int mt = 0; mt < 2; mt++){
                #pragma unroll
                for (int h = 0; h < 2; h++){
                    float m = mrun[mt][h], s = srun[mt][h];
                    #pragma unroll
                    for (int o = 1; o <= 2; o <<= 1){
                        float mo = __shfl_xor_sync(0xffffffffu, m, o);
                        float so = __shfl_xor_sync(0xffffffffu, s, o);
                        float nm = fmaxf(m, mo);
                        s = s * ex2a(fmaxf(m - nm, -126.f)) + so * ex2a(fmaxf(mo - nm, -126.f));
                        m = nm;
                    }
                    if (t == 0) part[cwp*128 + rw*32 + mt*16 + g + 8*h] = make_float2(m, s);
                }
            }
        }

        __syncthreads();   // all pairs done; part[] visible
        if (!is_mma && cwp == 0){
            const int rl = rw*32 + lane;
            float2 p0 = part[0*128 + rl];
            float2 p1 = part[1*128 + rl];
            float m = fmaxf(p0.x, p1.x);
            float s = p0.y * ex2a(fmaxf(p0.x - m, -126.f)) + p1.y * ex2a(fmaxf(p1.x - m, -126.f));
            g_pm[(m0 + rl)*16 + cb_start] = m;
            g_ps[(m0 + rl)*16 + cb_start] = s;
        }

        if (havenext){ CP_WAIT0; __syncthreads(); buf ^= 1; }
        wi = seg_end;
    }
}

// ---------------- 5a: per-row loss + per-block partial sum (64 blocks) ----------------
__global__ void fin1_kernel(){
    const int r = blockIdx.x * 128 + threadIdx.x;
    const float4* pm4 = reinterpret_cast<const float4*>(&g_pm[r*16]);
    const float4* ps4 = reinterpret_cast<const float4*>(&g_ps[r*16]);
    float m = -INFINITY;
    float4 pm[4], ps[4];
    #pragma unroll
    for (int i = 0; i < 4; i++){
        pm[i] = pm4[i]; ps[i] = ps4[i];
        m = fmaxf(m, fmaxf(fmaxf(pm[i].x, pm[i].y), fmaxf(pm[i].z, pm[i].w)));
    }
    float s = 0.f;
    #pragma unroll
    for (int i = 0; i < 4; i++){
        s += ps[i].x * ex2a(fmaxf(pm[i].x - m, -126.f));
        s += ps[i].y * ex2a(fmaxf(pm[i].y - m, -126.f));
        s += ps[i].z * ex2a(fmaxf(pm[i].z - m, -126.f));
        s += ps[i].w * ex2a(fmaxf(pm[i].w - m, -126.f));
    }
    float loss = LN2F * (m + __log2f(s) - g_pd[r]);
    #pragma unroll
    for (int o = 16; o; o >>= 1) loss += __shfl_xor_sync(0xffffffffu, loss, o);
    __shared__ float sw[4];
    if ((threadIdx.x & 31) == 0) sw[threadIdx.x >> 5] = loss;
    __syncthreads();
    if (threadIdx.x == 0) g_bsum[blockIdx.x] = sw[0] + sw[1] + sw[2] + sw[3];
}

// ---------------- 5b: final sum ----------------
__global__ void fin2_kernel(float* __restrict__ out){
    float v = (threadIdx.x < FINB) ? g_bsum[threadIdx.x] : 0.f;
    #pragma unroll
    for (int o = 16; o; o >>= 1) v += __shfl_xor_sync(0xffffffffu, v, o);
    __shared__ float sw[2];
    if ((threadIdx.x & 31) == 0) sw[threadIdx.x >> 5] = v;
    __syncthreads();
    if (threadIdx.x == 0) out[0] = (sw[0] + sw[1]) / (float)P;
}

extern "C" void kernel_launch(void* const* d_in, const int* in_sizes, int n_in,
                              void* d_out, int out_size){
    const float* f1  = (const float*)d_in[0];
    const float* f2  = (const float*)d_in[1];
    const void*  map = d_in[2];

    cudaFuncSetAttribute(nce_main_kernel,
                         cudaFuncAttributeMaxDynamicSharedMemorySize, SMEM_TOTAL);

    detect_kernel<<<1, 256>>>((const int*)map);        // launch 1
    prepQ_kernel<<<P, 128>>>(f1, f2, map);             // launch 2
    prepKf_kernel<<<256, 256>>>(f2);                   // launch 3
    nce_main_kernel<<<NCTA, 512, SMEM_TOTAL>>>();      // launch 4 (ncu target)
    fin1_kernel<<<FINB, 128>>>();                      // launch 5
    fin2_kernel<<<1, 64>>>((float*)d_out);             // launch 6
}